// round 16
// baseline (speedup 1.0000x reference)
#include <cuda_runtime.h>

typedef unsigned long long ull;
#define BSZ 2
#define NN 50000
#define NEg 400000

__device__ float g_P[BSZ * NN * 256];     // combined msg/upd projections (ull2 interleave)
__device__ float g_Pn[BSZ * NN * 64];
__device__ float g_agg[BSZ * NN * 64];    // aggregated ex*silu_h, pair layout
__device__ float g_den[BSZ * NN];
__device__ float4 g_Wf4[256];   // fused W2@Wa1 as [c][j], float4 over j
__device__ float g_bf[16];      // b2@Wa1 + ba1
__device__ ull   g_Wn64[64 * 32];  // fused W2m@Wn1_bot
__device__ ull   g_bn64[32];       // b2m@Wn1_bot pairs

__device__ __forceinline__ ull fma2(ull a, ull b, ull c) {
    ull d; asm("fma.rn.f32x2 %0, %1, %2, %3;" : "=l"(d) : "l"(a), "l"(b), "l"(c)); return d;
}
__device__ __forceinline__ ull add2(ull a, ull b) {
    ull d; asm("add.rn.f32x2 %0, %1, %2;" : "=l"(d) : "l"(a), "l"(b)); return d;
}
__device__ __forceinline__ ull pk2(float x, float y) {
    ull r; asm("mov.b64 %0, {%1, %2};" : "=l"(r) : "f"(x), "f"(y)); return r;
}
__device__ __forceinline__ ull dup2(float x) {
    ull r; asm("mov.b64 %0, {%1, %1};" : "=l"(r) : "f"(x)); return r;
}
__device__ __forceinline__ float2 up2(ull v) {
    float2 r; asm("mov.b64 {%0, %1}, %2;" : "=f"(r.x), "=f"(r.y) : "l"(v)); return r;
}
__device__ __forceinline__ float silu_f(float x) { return x / (1.f + __expf(-x)); }
__device__ __forceinline__ void red2(float* p, float a, float b) {
    asm volatile("red.global.add.v2.f32 [%0], {%1,%2};" :: "l"(p), "f"(a), "f"(b) : "memory");
}

// merged weight-fusion kernel (Wf/bf + Wn64/bn64)
__global__ void k_fuseall(const float* __restrict__ W2, const float* __restrict__ b2,
                          const float* __restrict__ Wa1, const float* __restrict__ ba1,
                          const float* __restrict__ Wn1bot) {
    int idx = blockIdx.x * blockDim.x + threadIdx.x;
    if (idx < 1024) {
        int c = idx >> 4, j = idx & 15;
        float s = 0.f;
        for (int d = 0; d < 128; d++) s += W2[c * 128 + d] * Wa1[d * 16 + j];
        ((float*)g_Wf4)[c * 16 + j] = s;
    }
    if (idx < 16) {
        float s = ba1[idx];
        for (int d = 0; d < 128; d++) s += b2[d] * Wa1[d * 16 + idx];
        g_bf[idx] = s;
    }
    if (idx >= 1024 && idx < 1024 + 2048) {
        int t = idx - 1024;
        int p = t >> 5, l = t & 31;
        int c = (p & 1) ? 32 + (p >> 1) : (p >> 1);
        float s0 = 0.f, s1 = 0.f;
        for (int o = 0; o < 128; o++) {
            float w2v = W2[c * 128 + o];
            s0 += w2v * Wn1bot[o * 64 + l];
            s1 += w2v * Wn1bot[o * 64 + l + 32];
        }
        g_Wn64[p * 32 + l] = pk2(s0, s1);
    }
    if (idx >= 1024 + 2048 && idx < 1024 + 2048 + 32) {
        int t = idx - (1024 + 2048);
        float s0 = 0.f, s1 = 0.f;
        for (int o = 0; o < 128; o++) {
            s0 += b2[o] * Wn1bot[o * 64 + t];
            s1 += b2[o] * Wn1bot[o * 64 + t + 32];
        }
        g_bn64[t] = pk2(s0, s1);
    }
}

// Fused node precompute (msg S/R + upd S/R + node-top) + agg/den zero-init.
__global__ void __launch_bounds__(512, 1)
k_npre3(const float* __restrict__ V, const float* __restrict__ Wm1,
        const float* __restrict__ Wu1, const float* __restrict__ Wn1,
        float* __restrict__ P, float* __restrict__ Pn) {
    extern __shared__ float sm[];
    ull* sWm = (ull*)sm;                 // 8192 ull: S block, R block
    ull* sWu = sWm + 8192;
    ull* sWn = sWu + 8192;               // 4096 ull
    float* sV = sm + 40960;              // 16 warps * 512 floats

    for (int i = threadIdx.x; i < 128 * 32; i += 512) {
        int k = i >> 5, l = i & 31;
        int pos = (k >> 1) * 64 + l * 2 + (k & 1);
        sWm[pos]        = pk2(Wm1[k * 64 + l],         Wm1[k * 64 + l + 32]);
        sWm[4096 + pos] = pk2(Wm1[(128 + k) * 64 + l], Wm1[(128 + k) * 64 + l + 32]);
        sWu[pos]        = pk2(Wu1[k * 64 + l],         Wu1[k * 64 + l + 32]);
        sWu[4096 + pos] = pk2(Wu1[(128 + k) * 64 + l], Wu1[(128 + k) * 64 + l + 32]);
        sWn[pos]        = pk2(Wn1[k * 64 + l],         Wn1[k * 64 + l + 32]);
    }
    __syncthreads();
    const int warp = threadIdx.x >> 5, l = threadIdx.x & 31;
    const float4* fmS = (const float4*)sWm;
    const float4* fmR = fmS + 2048;
    const float4* fuS = (const float4*)sWu;
    const float4* fuR = fuS + 2048;
    const float4* fnS = (const float4*)sWn;
    float4* sVq4 = (float4*)(sV + warp * 512);
    const float4* V4 = (const float4*)V;
    ulonglong2* P2 = (ulonglong2*)P;
    ull* PnU = (ull*)Pn;
    const float4 z4 = make_float4(0.f, 0.f, 0.f, 0.f);

    const int nchunks = (BSZ * NN) / 4;   // 25000
    const int wstride = gridDim.x * 16;
    for (int w = blockIdx.x * 16 + warp; w < nchunks; w += wstride) {
        const int r0 = w * 4;
        __syncwarp();
#pragma unroll
        for (int r = 0; r < 4; r++) sVq4[r * 32 + l] = __ldcs(V4 + (size_t)(r0 + r) * 32 + l);
        __syncwarp();
        ull am[4], bm[4], au[4], bu[4], an[4];
#pragma unroll
        for (int r = 0; r < 4; r++) { am[r] = 0ULL; bm[r] = 0ULL; au[r] = 0ULL; bu[r] = 0ULL; an[r] = 0ULL; }
#pragma unroll 2
        for (int k4 = 0; k4 < 32; k4++) {
            float4 mS0 = fmS[(2 * k4) * 32 + l], mS1 = fmS[(2 * k4 + 1) * 32 + l];
            float4 mR0 = fmR[(2 * k4) * 32 + l], mR1 = fmR[(2 * k4 + 1) * 32 + l];
            float4 uS0 = fuS[(2 * k4) * 32 + l], uS1 = fuS[(2 * k4 + 1) * 32 + l];
            float4 uR0 = fuR[(2 * k4) * 32 + l], uR1 = fuR[(2 * k4 + 1) * 32 + l];
            float4 nS0 = fnS[(2 * k4) * 32 + l], nS1 = fnS[(2 * k4 + 1) * 32 + l];
            ull wmS[4] = {pk2(mS0.x, mS0.y), pk2(mS0.z, mS0.w), pk2(mS1.x, mS1.y), pk2(mS1.z, mS1.w)};
            ull wmR[4] = {pk2(mR0.x, mR0.y), pk2(mR0.z, mR0.w), pk2(mR1.x, mR1.y), pk2(mR1.z, mR1.w)};
            ull wuS[4] = {pk2(uS0.x, uS0.y), pk2(uS0.z, uS0.w), pk2(uS1.x, uS1.y), pk2(uS1.z, uS1.w)};
            ull wuR[4] = {pk2(uR0.x, uR0.y), pk2(uR0.z, uR0.w), pk2(uR1.x, uR1.y), pk2(uR1.z, uR1.w)};
            ull wnS[4] = {pk2(nS0.x, nS0.y), pk2(nS0.z, nS0.w), pk2(nS1.x, nS1.y), pk2(nS1.z, nS1.w)};
#pragma unroll
            for (int r = 0; r < 4; r++) {
                float4 v = sVq4[r * 32 + k4];
                am[r] = fma2(dup2(v.x), wmS[0], am[r]); am[r] = fma2(dup2(v.y), wmS[1], am[r]);
                am[r] = fma2(dup2(v.z), wmS[2], am[r]); am[r] = fma2(dup2(v.w), wmS[3], am[r]);
                bm[r] = fma2(dup2(v.x), wmR[0], bm[r]); bm[r] = fma2(dup2(v.y), wmR[1], bm[r]);
                bm[r] = fma2(dup2(v.z), wmR[2], bm[r]); bm[r] = fma2(dup2(v.w), wmR[3], bm[r]);
                au[r] = fma2(dup2(v.x), wuS[0], au[r]); au[r] = fma2(dup2(v.y), wuS[1], au[r]);
                au[r] = fma2(dup2(v.z), wuS[2], au[r]); au[r] = fma2(dup2(v.w), wuS[3], au[r]);
                bu[r] = fma2(dup2(v.x), wuR[0], bu[r]); bu[r] = fma2(dup2(v.y), wuR[1], bu[r]);
                bu[r] = fma2(dup2(v.z), wuR[2], bu[r]); bu[r] = fma2(dup2(v.w), wuR[3], bu[r]);
                an[r] = fma2(dup2(v.x), wnS[0], an[r]); an[r] = fma2(dup2(v.y), wnS[1], an[r]);
                an[r] = fma2(dup2(v.z), wnS[2], an[r]); an[r] = fma2(dup2(v.w), wnS[3], an[r]);
            }
        }
#pragma unroll
        for (int r = 0; r < 4; r++) {
            size_t row = r0 + r;
            P2[row * 64 + l]      = make_ulonglong2(am[r], au[r]);
            P2[row * 64 + 32 + l] = make_ulonglong2(bm[r], bu[r]);
            PnU[row * 32 + l]     = an[r];
            if (l < 16) ((float4*)g_agg)[row * 16 + l] = z4;   // zero-init agg
        }
        if (l < 4) g_den[r0 + l] = 0.f;                         // zero-init den
    }
}

// Fused edge kernel; 640 threads (20 warps/SM), no E register-prefetch.
__global__ void __launch_bounds__(640, 1)
k_edge_fused(const float* __restrict__ E, const int* __restrict__ edges,
             const float* __restrict__ Wm1, const float* __restrict__ bm1,
             const float* __restrict__ Wu1, const float* __restrict__ bu1,
             const float* __restrict__ Wu2, const float* __restrict__ bu2,
             const float* __restrict__ Wa2, const float* __restrict__ ba2,
             const float* __restrict__ P, float* __restrict__ outE) {
    extern __shared__ float sm[];
    ull*    sWm  = (ull*)sm;
    float4* sWmf = (float4*)sm;
    ull*    sWu  = (ull*)(sm + 8192);
    float4* sWuf = (float4*)(sm + 8192);
    float4* sW2f = (float4*)(sm + 16384);
    float4* sWfF = (float4*)(sm + 24576);
    float*  sBf  = sm + 25600;
    float*  sWa2s= sm + 25616;
    float*  sU   = sm + 25632;               // 20 warps * 1024 floats

    for (int i = threadIdx.x; i < 128 * 32; i += 640) {
        int k = i >> 5, l = i & 31;
        int pos = (k >> 1) * 64 + l * 2 + (k & 1);
        sWm[pos] = pk2(Wm1[(256 + k) * 64 + l], Wm1[(256 + k) * 64 + l + 32]);
        sWu[pos] = pk2(Wu1[(256 + k) * 64 + l], Wu1[(256 + k) * 64 + l + 32]);
    }
    for (int i = threadIdx.x; i < 64 * 32; i += 640) {
        int j = i >> 5, l = i & 31;
        sW2f[i] = make_float4(Wu2[j * 128 + 4 * l], Wu2[j * 128 + 4 * l + 1],
                              Wu2[j * 128 + 4 * l + 2], Wu2[j * 128 + 4 * l + 3]);
    }
    for (int i = threadIdx.x; i < 256; i += 640) sWfF[i] = g_Wf4[i];
    if (threadIdx.x < 16) { sBf[threadIdx.x] = g_bf[threadIdx.x]; sWa2s[threadIdx.x] = __ldg(Wa2 + threadIdx.x); }
    const int warp = threadIdx.x >> 5, l = threadIdx.x & 31;
    const ull bbm  = pk2(__ldg(bm1 + l), __ldg(bm1 + l + 32));
    const ull bbuu = pk2(__ldg(bu1 + l), __ldg(bu1 + l + 32));
    const ull b2lo = pk2(__ldg(bu2 + 4 * l), __ldg(bu2 + 4 * l + 1));
    const ull b2hi = pk2(__ldg(bu2 + 4 * l + 2), __ldg(bu2 + 4 * l + 3));
    const float ba2v = __ldg(ba2);
    __syncthreads();

    float* sQ = sU + warp * 1024;
    const float4* sQ4 = (const float4*)sQ;
    float* sHw = sQ;   // stride 76 per edge row
    const float4* E4 = (const float4*)E;
    const int nchunks = (BSZ * NEg) / 8;
    const int wstride = gridDim.x * 20;
    for (int w = blockIdx.x * 20 + warp; w < nchunks; w += wstride) {
        __syncwarp();
#pragma unroll
        for (int j = 0; j < 8; j++)
            ((float4*)sQ)[j * 32 + l] = __ldcs(E4 + (size_t)w * 256 + j * 32 + l);
        const int ge0 = w * 8;
        const int b = ge0 / NEg;
        int rx[8];
        ull hm[8], hu[8];
        const int2* edp = (const int2*)edges + ge0;
        const ulonglong2* Pu2 = (const ulonglong2*)P + (size_t)b * NN * 64;
#pragma unroll
        for (int e = 0; e < 8; e++) {
            int2 t2 = __ldg(edp + e);
            rx[e] = t2.y;
            ulonglong2 s2 = __ldg(Pu2 + (size_t)t2.x * 64 + l);
            ulonglong2 r2 = __ldg(Pu2 + (size_t)t2.y * 64 + 32 + l);
            hm[e] = add2(add2(s2.x, r2.x), bbm);
            hu[e] = add2(add2(s2.y, r2.y), bbuu);
        }
        __syncwarp();
#pragma unroll 4
        for (int k4 = 0; k4 < 32; k4++) {
            float4 ua = sWuf[(2 * k4) * 32 + l];
            float4 ub = sWuf[(2 * k4 + 1) * 32 + l];
            float4 ma_ = sWmf[(2 * k4) * 32 + l];
            float4 mb_ = sWmf[(2 * k4 + 1) * 32 + l];
            ull uw0 = pk2(ua.x, ua.y), uw1 = pk2(ua.z, ua.w);
            ull uw2 = pk2(ub.x, ub.y), uw3 = pk2(ub.z, ub.w);
            ull mw0 = pk2(ma_.x, ma_.y), mw1 = pk2(ma_.z, ma_.w);
            ull mw2 = pk2(mb_.x, mb_.y), mw3 = pk2(mb_.z, mb_.w);
#pragma unroll
            for (int e = 0; e < 8; e++) {
                float4 ev = sQ4[e * 32 + k4];
                ull dx = dup2(ev.x), dy = dup2(ev.y), dz = dup2(ev.z), dw = dup2(ev.w);
                hu[e] = fma2(dx, uw0, hu[e]);
                hu[e] = fma2(dy, uw1, hu[e]);
                hu[e] = fma2(dz, uw2, hu[e]);
                hu[e] = fma2(dw, uw3, hu[e]);
                hm[e] = fma2(dx, mw0, hm[e]);
                hm[e] = fma2(dy, mw1, hm[e]);
                hm[e] = fma2(dz, mw2, hm[e]);
                hm[e] = fma2(dw, mw3, hm[e]);
            }
        }
        __syncwarp();
        float2 SH[8];
#pragma unroll
        for (int e = 0; e < 8; e++) {
            float2 hh = up2(hm[e]);
            SH[e].x = silu_f(hh.x); SH[e].y = silu_f(hh.y);
            sHw[e * 76 + l] = SH[e].x;
            sHw[e * 76 + l + 32] = SH[e].y;
        }
        __syncwarp();
        {
            const int e_att = l & 7, jg = l >> 3;
            const float* shrow = sHw + e_att * 76;
            float p0 = 0.f, p1 = 0.f, p2 = 0.f, p3 = 0.f;
#pragma unroll 8
            for (int c = 0; c < 64; c++) {
                float shc = shrow[c];
                float4 wfv = sWfF[c * 4 + jg];
                p0 += shc * wfv.x; p1 += shc * wfv.y;
                p2 += shc * wfv.z; p3 += shc * wfv.w;
            }
            float s = silu_f(p0 + sBf[jg * 4 + 0]) * sWa2s[jg * 4 + 0]
                    + silu_f(p1 + sBf[jg * 4 + 1]) * sWa2s[jg * 4 + 1]
                    + silu_f(p2 + sBf[jg * 4 + 2]) * sWa2s[jg * 4 + 2]
                    + silu_f(p3 + sBf[jg * 4 + 3]) * sWa2s[jg * 4 + 3];
            s += __shfl_xor_sync(0xffffffffu, s, 8);
            s += __shfl_xor_sync(0xffffffffu, s, 16);
            float logit = fminf(30.f, fmaxf(-30.f, ba2v + s));
            float exf = __expf(logit);
            float ex[8];
#pragma unroll
            for (int e = 0; e < 8; e++) ex[e] = __shfl_sync(0xffffffffu, exf, e);
#pragma unroll
            for (int e = 0; e < 8; e++) {
                float* ap = g_agg + (size_t)(b * NN + rx[e]) * 64 + 2 * l;
                red2(ap, ex[e] * SH[e].x, ex[e] * SH[e].y);
            }
            if (l < 8) {
                int2 t2 = __ldg(edp + l);
                atomicAdd(&g_den[b * NN + t2.y], exf);
            }
        }
        __syncwarp();
#pragma unroll
        for (int e = 0; e < 8; e++) {
            float2 hh = up2(hu[e]);
            sHw[e * 76 + l] = silu_f(hh.x);
            sHw[e * 76 + l + 32] = silu_f(hh.y);
        }
        __syncwarp();
        ull ma[8], mb[8];
#pragma unroll
        for (int e = 0; e < 8; e++) { ma[e] = b2lo; mb[e] = b2hi; }
#pragma unroll 2
        for (int c4 = 0; c4 < 16; c4++) {
            float4 hh[8];
#pragma unroll
            for (int e = 0; e < 8; e++) hh[e] = *(const float4*)(sHw + e * 76 + 4 * c4);
#pragma unroll
            for (int ci = 0; ci < 4; ci++) {
                int c = 4 * c4 + ci;
                float4 wv = sW2f[c * 32 + l];
                ull wlo = pk2(wv.x, wv.y), whi = pk2(wv.z, wv.w);
#pragma unroll
                for (int e = 0; e < 8; e++) {
                    float hv = (ci == 0) ? hh[e].x : (ci == 1) ? hh[e].y : (ci == 2) ? hh[e].z : hh[e].w;
                    ull d = dup2(hv);
                    ma[e] = fma2(d, wlo, ma[e]);
                    mb[e] = fma2(d, whi, mb[e]);
                }
            }
        }
#pragma unroll
        for (int e = 0; e < 8; e++) {
            float2 MA = up2(ma[e]), MB = up2(mb[e]);
            __stcs((float4*)outE + (size_t)(ge0 + e) * 32 + l,
                   make_float4(MA.x, MA.y, MB.x, MB.y));
        }
    }
}

// node output MLP
__global__ void __launch_bounds__(256, 2)
k_nodeout(const float* __restrict__ bn1, const float* __restrict__ Wn2,
          const float* __restrict__ bn2, float* __restrict__ outN) {
    extern __shared__ float sm[];
    ull*    sW1u = (ull*)sm;
    float4* sW2f = (float4*)(sm + 4096);
    float*  sH   = sm + 12288;
    for (int i = threadIdx.x; i < 64 * 32; i += 256) sW1u[i] = g_Wn64[i];
    for (int i = threadIdx.x; i < 64 * 32; i += 256) {
        int j = i >> 5, l = i & 31;
        sW2f[i] = make_float4(Wn2[j * 128 + 4 * l], Wn2[j * 128 + 4 * l + 1],
                              Wn2[j * 128 + 4 * l + 2], Wn2[j * 128 + 4 * l + 3]);
    }
    const int warp = threadIdx.x >> 5, l = threadIdx.x & 31;
    const ull bbu   = pk2(__ldg(bn1 + l), __ldg(bn1 + l + 32));
    const ull baddu = g_bn64[l];
    const ull b2lo = pk2(__ldg(bn2 + 4 * l), __ldg(bn2 + 4 * l + 1));
    const ull b2hi = pk2(__ldg(bn2 + 4 * l + 2), __ldg(bn2 + 4 * l + 3));
    __syncthreads();

    float* sHw = sH + warp * 576;
    const ull* Pnu = (const ull*)g_Pn;
    const int nchunks = (BSZ * NN) / 8;
    for (int w = blockIdx.x * 8 + warp; w < nchunks; w += gridDim.x * 8) {
        const int r0 = w * 8;
        float den8[8];
        ull pn[8];
#pragma unroll
        for (int e = 0; e < 8; e++) {
            den8[e] = __ldg(g_den + r0 + e);
            pn[e] = __ldg(Pnu + (size_t)(r0 + e) * 32 + l);
        }
        ull h[8] = {0ULL, 0ULL, 0ULL, 0ULL, 0ULL, 0ULL, 0ULL, 0ULL};
        const float4* Af = (const float4*)g_agg + (size_t)r0 * 16;
#pragma unroll 4
        for (int k4 = 0; k4 < 16; k4++) {
            ull wk[4];
#pragma unroll
            for (int ki = 0; ki < 4; ki++) wk[ki] = sW1u[(k4 * 4 + ki) * 32 + l];
#pragma unroll
            for (int e = 0; e < 8; e++) {
                float4 v = __ldcs(Af + e * 16 + k4);
                h[e] = fma2(dup2(v.x), wk[0], h[e]);
                h[e] = fma2(dup2(v.y), wk[1], h[e]);
                h[e] = fma2(dup2(v.z), wk[2], h[e]);
                h[e] = fma2(dup2(v.w), wk[3], h[e]);
            }
        }
        __syncwarp();
#pragma unroll
        for (int e = 0; e < 8; e++) {
            float nz = den8[e] != 0.f ? 1.f : 0.f;
            float inv = den8[e] != 0.f ? 1.f / den8[e] : 0.f;
            ull base = add2(pn[e], bbu);
            base = fma2(dup2(nz), baddu, base);
            float2 hh = up2(fma2(dup2(inv), h[e], base));
            sHw[e * 72 + l] = silu_f(hh.x);
            sHw[e * 72 + l + 32] = silu_f(hh.y);
        }
        __syncwarp();
        ull ma[8], mb[8];
#pragma unroll
        for (int e = 0; e < 8; e++) { ma[e] = b2lo; mb[e] = b2hi; }
#pragma unroll 2
        for (int c4 = 0; c4 < 16; c4++) {
            float4 hh[8];
#pragma unroll
            for (int e = 0; e < 8; e++) hh[e] = *(const float4*)(sHw + e * 72 + 4 * c4);
#pragma unroll
            for (int ci = 0; ci < 4; ci++) {
                int c = 4 * c4 + ci;
                float4 wv = sW2f[c * 32 + l];
                ull wlo = pk2(wv.x, wv.y), whi = pk2(wv.z, wv.w);
#pragma unroll
                for (int e = 0; e < 8; e++) {
                    float hv = (ci == 0) ? hh[e].x : (ci == 1) ? hh[e].y : (ci == 2) ? hh[e].z : hh[e].w;
                    ull d = dup2(hv);
                    ma[e] = fma2(d, wlo, ma[e]);
                    mb[e] = fma2(d, whi, mb[e]);
                }
            }
        }
#pragma unroll
        for (int e = 0; e < 8; e++) {
            float2 MA = up2(ma[e]), MB = up2(mb[e]);
            __stcs((float4*)outN + (size_t)(r0 + e) * 32 + l,
                   make_float4(MA.x, MA.y, MB.x, MB.y));
        }
        __syncwarp();
    }
}

extern "C" void kernel_launch(void* const* d_in, const int* in_sizes, int n_in,
                              void* d_out, int out_size) {
    const float* V = (const float*)d_in[0];
    const float* E = (const float*)d_in[1];
    const int* edges = (const int*)d_in[2];
    const float* Wm1 = (const float*)d_in[3];
    const float* bm1 = (const float*)d_in[4];
    const float* Wm2 = (const float*)d_in[5];
    const float* bm2 = (const float*)d_in[6];
    const float* Wa1 = (const float*)d_in[7];
    const float* ba1 = (const float*)d_in[8];
    const float* Wa2 = (const float*)d_in[9];
    const float* ba2 = (const float*)d_in[10];
    const float* Wu1 = (const float*)d_in[11];
    const float* bu1 = (const float*)d_in[12];
    const float* Wu2 = (const float*)d_in[13];
    const float* bu2 = (const float*)d_in[14];
    const float* Wn1 = (const float*)d_in[15];
    const float* bn1 = (const float*)d_in[16];
    const float* Wn2 = (const float*)d_in[17];
    const float* bn2 = (const float*)d_in[18];
    float* outN = (float*)d_out;
    float* outE = outN + (size_t)BSZ * NN * 128;

    float* Pc; cudaGetSymbolAddress((void**)&Pc, g_P);
    float* Pn; cudaGetSymbolAddress((void**)&Pn, g_Pn);

    cudaFuncSetAttribute(k_npre3, cudaFuncAttributeMaxDynamicSharedMemorySize, 196608);
    cudaFuncSetAttribute(k_edge_fused, cudaFuncAttributeMaxDynamicSharedMemorySize, 184448);
    cudaFuncSetAttribute(k_nodeout, cudaFuncAttributeMaxDynamicSharedMemorySize, 67584);

    k_fuseall<<<13, 256>>>(Wm2, bm2, Wa1, ba1, Wn1 + 128 * 64);
    k_npre3<<<148, 512, 196608>>>(V, Wm1, Wu1, Wn1, Pc, Pn);
    k_edge_fused<<<148, 640, 184448>>>(E, edges, Wm1, bm1, Wu1, bu1, Wu2, bu2, Wa2, ba2, Pc, outE);
    k_nodeout<<<592, 256, 67584>>>(bn1, Wn2, bn2, outN);
}

// round 17
// speedup vs baseline: 1.0332x; 1.0332x over previous
#include <cuda_runtime.h>

typedef unsigned long long ull;
#define BSZ 2
#define NN 50000
#define NEg 400000

__device__ float g_P[BSZ * NN * 256];     // combined msg/upd projections (ull2 interleave)
__device__ float g_Pn[BSZ * NN * 64];
__device__ float g_agg[BSZ * NN * 64];    // aggregated ex*silu_h, pair layout
__device__ float g_den[BSZ * NN];
__device__ float4 g_Wf4[256];   // fused W2@Wa1 as [c][j], float4 over j
__device__ float g_bf[16];      // b2@Wa1 + ba1
__device__ ull   g_Wn64[64 * 32];  // fused W2m@Wn1_bot
__device__ ull   g_bn64[32];       // b2m@Wn1_bot pairs

__device__ __forceinline__ ull fma2(ull a, ull b, ull c) {
    ull d; asm("fma.rn.f32x2 %0, %1, %2, %3;" : "=l"(d) : "l"(a), "l"(b), "l"(c)); return d;
}
__device__ __forceinline__ ull add2(ull a, ull b) {
    ull d; asm("add.rn.f32x2 %0, %1, %2;" : "=l"(d) : "l"(a), "l"(b)); return d;
}
__device__ __forceinline__ ull pk2(float x, float y) {
    ull r; asm("mov.b64 %0, {%1, %2};" : "=l"(r) : "f"(x), "f"(y)); return r;
}
__device__ __forceinline__ ull dup2(float x) {
    ull r; asm("mov.b64 %0, {%1, %1};" : "=l"(r) : "f"(x)); return r;
}
__device__ __forceinline__ float2 up2(ull v) {
    float2 r; asm("mov.b64 {%0, %1}, %2;" : "=f"(r.x), "=f"(r.y) : "l"(v)); return r;
}
__device__ __forceinline__ float silu_f(float x) { return x / (1.f + __expf(-x)); }
__device__ __forceinline__ void red2(float* p, float a, float b) {
    asm volatile("red.global.add.v2.f32 [%0], {%1,%2};" :: "l"(p), "f"(a), "f"(b) : "memory");
}

// merged weight-fusion kernel (Wf/bf + Wn64/bn64)
__global__ void k_fuseall(const float* __restrict__ W2, const float* __restrict__ b2,
                          const float* __restrict__ Wa1, const float* __restrict__ ba1,
                          const float* __restrict__ Wn1bot) {
    int idx = blockIdx.x * blockDim.x + threadIdx.x;
    if (idx < 1024) {
        int c = idx >> 4, j = idx & 15;
        float s = 0.f;
        for (int d = 0; d < 128; d++) s += W2[c * 128 + d] * Wa1[d * 16 + j];
        ((float*)g_Wf4)[c * 16 + j] = s;
    }
    if (idx < 16) {
        float s = ba1[idx];
        for (int d = 0; d < 128; d++) s += b2[d] * Wa1[d * 16 + idx];
        g_bf[idx] = s;
    }
    if (idx >= 1024 && idx < 1024 + 2048) {
        int t = idx - 1024;
        int p = t >> 5, l = t & 31;
        int c = (p & 1) ? 32 + (p >> 1) : (p >> 1);
        float s0 = 0.f, s1 = 0.f;
        for (int o = 0; o < 128; o++) {
            float w2v = W2[c * 128 + o];
            s0 += w2v * Wn1bot[o * 64 + l];
            s1 += w2v * Wn1bot[o * 64 + l + 32];
        }
        g_Wn64[p * 32 + l] = pk2(s0, s1);
    }
    if (idx >= 1024 + 2048 && idx < 1024 + 2048 + 32) {
        int t = idx - (1024 + 2048);
        float s0 = 0.f, s1 = 0.f;
        for (int o = 0; o < 128; o++) {
            s0 += b2[o] * Wn1bot[o * 64 + t];
            s1 += b2[o] * Wn1bot[o * 64 + t + 32];
        }
        g_bn64[t] = pk2(s0, s1);
    }
}

// Fused node precompute (msg S/R + upd S/R + node-top) + agg/den zero-init.
__global__ void __launch_bounds__(512, 1)
k_npre3(const float* __restrict__ V, const float* __restrict__ Wm1,
        const float* __restrict__ Wu1, const float* __restrict__ Wn1,
        float* __restrict__ P, float* __restrict__ Pn) {
    extern __shared__ float sm[];
    ull* sWm = (ull*)sm;                 // 8192 ull: S block, R block
    ull* sWu = sWm + 8192;
    ull* sWn = sWu + 8192;               // 4096 ull
    float* sV = sm + 40960;              // 16 warps * 512 floats

    for (int i = threadIdx.x; i < 128 * 32; i += 512) {
        int k = i >> 5, l = i & 31;
        int pos = (k >> 1) * 64 + l * 2 + (k & 1);
        sWm[pos]        = pk2(Wm1[k * 64 + l],         Wm1[k * 64 + l + 32]);
        sWm[4096 + pos] = pk2(Wm1[(128 + k) * 64 + l], Wm1[(128 + k) * 64 + l + 32]);
        sWu[pos]        = pk2(Wu1[k * 64 + l],         Wu1[k * 64 + l + 32]);
        sWu[4096 + pos] = pk2(Wu1[(128 + k) * 64 + l], Wu1[(128 + k) * 64 + l + 32]);
        sWn[pos]        = pk2(Wn1[k * 64 + l],         Wn1[k * 64 + l + 32]);
    }
    __syncthreads();
    const int warp = threadIdx.x >> 5, l = threadIdx.x & 31;
    const float4* fmS = (const float4*)sWm;
    const float4* fmR = fmS + 2048;
    const float4* fuS = (const float4*)sWu;
    const float4* fuR = fuS + 2048;
    const float4* fnS = (const float4*)sWn;
    float4* sVq4 = (float4*)(sV + warp * 512);
    const float4* V4 = (const float4*)V;
    ulonglong2* P2 = (ulonglong2*)P;
    ull* PnU = (ull*)Pn;
    const float4 z4 = make_float4(0.f, 0.f, 0.f, 0.f);

    const int nchunks = (BSZ * NN) / 4;   // 25000
    const int wstride = gridDim.x * 16;
    for (int w = blockIdx.x * 16 + warp; w < nchunks; w += wstride) {
        const int r0 = w * 4;
        __syncwarp();
#pragma unroll
        for (int r = 0; r < 4; r++) sVq4[r * 32 + l] = __ldcs(V4 + (size_t)(r0 + r) * 32 + l);
        __syncwarp();
        ull am[4], bm[4], au[4], bu[4], an[4];
#pragma unroll
        for (int r = 0; r < 4; r++) { am[r] = 0ULL; bm[r] = 0ULL; au[r] = 0ULL; bu[r] = 0ULL; an[r] = 0ULL; }
#pragma unroll 2
        for (int k4 = 0; k4 < 32; k4++) {
            float4 mS0 = fmS[(2 * k4) * 32 + l], mS1 = fmS[(2 * k4 + 1) * 32 + l];
            float4 mR0 = fmR[(2 * k4) * 32 + l], mR1 = fmR[(2 * k4 + 1) * 32 + l];
            float4 uS0 = fuS[(2 * k4) * 32 + l], uS1 = fuS[(2 * k4 + 1) * 32 + l];
            float4 uR0 = fuR[(2 * k4) * 32 + l], uR1 = fuR[(2 * k4 + 1) * 32 + l];
            float4 nS0 = fnS[(2 * k4) * 32 + l], nS1 = fnS[(2 * k4 + 1) * 32 + l];
            ull wmS[4] = {pk2(mS0.x, mS0.y), pk2(mS0.z, mS0.w), pk2(mS1.x, mS1.y), pk2(mS1.z, mS1.w)};
            ull wmR[4] = {pk2(mR0.x, mR0.y), pk2(mR0.z, mR0.w), pk2(mR1.x, mR1.y), pk2(mR1.z, mR1.w)};
            ull wuS[4] = {pk2(uS0.x, uS0.y), pk2(uS0.z, uS0.w), pk2(uS1.x, uS1.y), pk2(uS1.z, uS1.w)};
            ull wuR[4] = {pk2(uR0.x, uR0.y), pk2(uR0.z, uR0.w), pk2(uR1.x, uR1.y), pk2(uR1.z, uR1.w)};
            ull wnS[4] = {pk2(nS0.x, nS0.y), pk2(nS0.z, nS0.w), pk2(nS1.x, nS1.y), pk2(nS1.z, nS1.w)};
#pragma unroll
            for (int r = 0; r < 4; r++) {
                float4 v = sVq4[r * 32 + k4];
                am[r] = fma2(dup2(v.x), wmS[0], am[r]); am[r] = fma2(dup2(v.y), wmS[1], am[r]);
                am[r] = fma2(dup2(v.z), wmS[2], am[r]); am[r] = fma2(dup2(v.w), wmS[3], am[r]);
                bm[r] = fma2(dup2(v.x), wmR[0], bm[r]); bm[r] = fma2(dup2(v.y), wmR[1], bm[r]);
                bm[r] = fma2(dup2(v.z), wmR[2], bm[r]); bm[r] = fma2(dup2(v.w), wmR[3], bm[r]);
                au[r] = fma2(dup2(v.x), wuS[0], au[r]); au[r] = fma2(dup2(v.y), wuS[1], au[r]);
                au[r] = fma2(dup2(v.z), wuS[2], au[r]); au[r] = fma2(dup2(v.w), wuS[3], au[r]);
                bu[r] = fma2(dup2(v.x), wuR[0], bu[r]); bu[r] = fma2(dup2(v.y), wuR[1], bu[r]);
                bu[r] = fma2(dup2(v.z), wuR[2], bu[r]); bu[r] = fma2(dup2(v.w), wuR[3], bu[r]);
                an[r] = fma2(dup2(v.x), wnS[0], an[r]); an[r] = fma2(dup2(v.y), wnS[1], an[r]);
                an[r] = fma2(dup2(v.z), wnS[2], an[r]); an[r] = fma2(dup2(v.w), wnS[3], an[r]);
            }
        }
#pragma unroll
        for (int r = 0; r < 4; r++) {
            size_t row = r0 + r;
            P2[row * 64 + l]      = make_ulonglong2(am[r], au[r]);
            P2[row * 64 + 32 + l] = make_ulonglong2(bm[r], bu[r]);
            PnU[row * 32 + l]     = an[r];
            if (l < 16) ((float4*)g_agg)[row * 16 + l] = z4;   // zero-init agg
        }
        if (l < 4) g_den[r0 + l] = 0.f;                         // zero-init den
    }
}

// Fused edge kernel; 512 threads, E register-prefetch, merged stage-1, stride-76 sHw.
__global__ void __launch_bounds__(512, 1)
k_edge_fused(const float* __restrict__ E, const int* __restrict__ edges,
             const float* __restrict__ Wm1, const float* __restrict__ bm1,
             const float* __restrict__ Wu1, const float* __restrict__ bu1,
             const float* __restrict__ Wu2, const float* __restrict__ bu2,
             const float* __restrict__ Wa2, const float* __restrict__ ba2,
             const float* __restrict__ P, float* __restrict__ outE) {
    extern __shared__ float sm[];
    ull*    sWm  = (ull*)sm;
    float4* sWmf = (float4*)sm;
    ull*    sWu  = (ull*)(sm + 8192);
    float4* sWuf = (float4*)(sm + 8192);
    float4* sW2f = (float4*)(sm + 16384);
    float4* sWfF = (float4*)(sm + 24576);
    float*  sBf  = sm + 25600;
    float*  sWa2s= sm + 25616;
    float*  sU   = sm + 25632;               // 16 warps * 1024 floats

    for (int i = threadIdx.x; i < 128 * 32; i += 512) {
        int k = i >> 5, l = i & 31;
        int pos = (k >> 1) * 64 + l * 2 + (k & 1);
        sWm[pos] = pk2(Wm1[(256 + k) * 64 + l], Wm1[(256 + k) * 64 + l + 32]);
        sWu[pos] = pk2(Wu1[(256 + k) * 64 + l], Wu1[(256 + k) * 64 + l + 32]);
    }
    for (int i = threadIdx.x; i < 64 * 32; i += 512) {
        int j = i >> 5, l = i & 31;
        sW2f[i] = make_float4(Wu2[j * 128 + 4 * l], Wu2[j * 128 + 4 * l + 1],
                              Wu2[j * 128 + 4 * l + 2], Wu2[j * 128 + 4 * l + 3]);
    }
    for (int i = threadIdx.x; i < 256; i += 512) sWfF[i] = g_Wf4[i];
    if (threadIdx.x < 16) { sBf[threadIdx.x] = g_bf[threadIdx.x]; sWa2s[threadIdx.x] = __ldg(Wa2 + threadIdx.x); }
    const int warp = threadIdx.x >> 5, l = threadIdx.x & 31;
    const ull bbm  = pk2(__ldg(bm1 + l), __ldg(bm1 + l + 32));
    const ull bbuu = pk2(__ldg(bu1 + l), __ldg(bu1 + l + 32));
    const ull b2lo = pk2(__ldg(bu2 + 4 * l), __ldg(bu2 + 4 * l + 1));
    const ull b2hi = pk2(__ldg(bu2 + 4 * l + 2), __ldg(bu2 + 4 * l + 3));
    const float ba2v = __ldg(ba2);
    __syncthreads();

    float* sQ = sU + warp * 1024;
    const float4* sQ4 = (const float4*)sQ;
    float* sHw = sQ;   // stride 76 per edge row
    const float4* E4 = (const float4*)E;
    const int nchunks = (BSZ * NEg) / 8;
    const int wstride = gridDim.x * 16;
    int w = blockIdx.x * 16 + warp;
    float4 ereg[8];
    if (w < nchunks) {
#pragma unroll
        for (int j = 0; j < 8; j++) ereg[j] = __ldcs(E4 + (size_t)w * 256 + j * 32 + l);
    }
    for (; w < nchunks; w += wstride) {
        __syncwarp();
#pragma unroll
        for (int j = 0; j < 8; j++) ((float4*)sQ)[j * 32 + l] = ereg[j];
        __syncwarp();
        const int ge0 = w * 8;
        const int b = ge0 / NEg;
        int rx[8];
        ull hm[8], hu[8];
        const int2* edp = (const int2*)edges + ge0;
        const ulonglong2* Pu2 = (const ulonglong2*)P + (size_t)b * NN * 64;
#pragma unroll
        for (int e = 0; e < 8; e++) {
            int2 t2 = __ldg(edp + e);
            rx[e] = t2.y;
            ulonglong2 s2 = __ldg(Pu2 + (size_t)t2.x * 64 + l);
            ulonglong2 r2 = __ldg(Pu2 + (size_t)t2.y * 64 + 32 + l);
            hm[e] = add2(add2(s2.x, r2.x), bbm);
            hu[e] = add2(add2(s2.y, r2.y), bbuu);
        }
#pragma unroll 4
        for (int k4 = 0; k4 < 32; k4++) {
            float4 ua = sWuf[(2 * k4) * 32 + l];
            float4 ub = sWuf[(2 * k4 + 1) * 32 + l];
            float4 ma_ = sWmf[(2 * k4) * 32 + l];
            float4 mb_ = sWmf[(2 * k4 + 1) * 32 + l];
            ull uw0 = pk2(ua.x, ua.y), uw1 = pk2(ua.z, ua.w);
            ull uw2 = pk2(ub.x, ub.y), uw3 = pk2(ub.z, ub.w);
            ull mw0 = pk2(ma_.x, ma_.y), mw1 = pk2(ma_.z, ma_.w);
            ull mw2 = pk2(mb_.x, mb_.y), mw3 = pk2(mb_.z, mb_.w);
#pragma unroll
            for (int e = 0; e < 8; e++) {
                float4 ev = sQ4[e * 32 + k4];
                ull dx = dup2(ev.x), dy = dup2(ev.y), dz = dup2(ev.z), dw = dup2(ev.w);
                hu[e] = fma2(dx, uw0, hu[e]);
                hu[e] = fma2(dy, uw1, hu[e]);
                hu[e] = fma2(dz, uw2, hu[e]);
                hu[e] = fma2(dw, uw3, hu[e]);
                hm[e] = fma2(dx, mw0, hm[e]);
                hm[e] = fma2(dy, mw1, hm[e]);
                hm[e] = fma2(dz, mw2, hm[e]);
                hm[e] = fma2(dw, mw3, hm[e]);
            }
        }
        {
            int wn = w + wstride;
            if (wn < nchunks) {
#pragma unroll
                for (int j = 0; j < 8; j++) ereg[j] = __ldcs(E4 + (size_t)wn * 256 + j * 32 + l);
            }
        }
        __syncwarp();
        float2 SH[8];
#pragma unroll
        for (int e = 0; e < 8; e++) {
            float2 hh = up2(hm[e]);
            SH[e].x = silu_f(hh.x); SH[e].y = silu_f(hh.y);
            sHw[e * 76 + l] = SH[e].x;
            sHw[e * 76 + l + 32] = SH[e].y;
        }
        __syncwarp();
        {
            const int e_att = l & 7, jg = l >> 3;
            const float* shrow = sHw + e_att * 76;
            float p0 = 0.f, p1 = 0.f, p2 = 0.f, p3 = 0.f;
#pragma unroll 8
            for (int c = 0; c < 64; c++) {
                float shc = shrow[c];
                float4 wfv = sWfF[c * 4 + jg];
                p0 += shc * wfv.x; p1 += shc * wfv.y;
                p2 += shc * wfv.z; p3 += shc * wfv.w;
            }
            float s = silu_f(p0 + sBf[jg * 4 + 0]) * sWa2s[jg * 4 + 0]
                    + silu_f(p1 + sBf[jg * 4 + 1]) * sWa2s[jg * 4 + 1]
                    + silu_f(p2 + sBf[jg * 4 + 2]) * sWa2s[jg * 4 + 2]
                    + silu_f(p3 + sBf[jg * 4 + 3]) * sWa2s[jg * 4 + 3];
            s += __shfl_xor_sync(0xffffffffu, s, 8);
            s += __shfl_xor_sync(0xffffffffu, s, 16);
            float logit = fminf(30.f, fmaxf(-30.f, ba2v + s));
            float exf = __expf(logit);
            float ex[8];
#pragma unroll
            for (int e = 0; e < 8; e++) ex[e] = __shfl_sync(0xffffffffu, exf, e);
#pragma unroll
            for (int e = 0; e < 8; e++) {
                float* ap = g_agg + (size_t)(b * NN + rx[e]) * 64 + 2 * l;
                red2(ap, ex[e] * SH[e].x, ex[e] * SH[e].y);
            }
            if (l < 8) {
                int2 t2 = __ldg(edp + l);
                atomicAdd(&g_den[b * NN + t2.y], exf);
            }
        }
        __syncwarp();
#pragma unroll
        for (int e = 0; e < 8; e++) {
            float2 hh = up2(hu[e]);
            sHw[e * 76 + l] = silu_f(hh.x);
            sHw[e * 76 + l + 32] = silu_f(hh.y);
        }
        __syncwarp();
        ull ma[8], mb[8];
#pragma unroll
        for (int e = 0; e < 8; e++) { ma[e] = b2lo; mb[e] = b2hi; }
#pragma unroll 2
        for (int c4 = 0; c4 < 16; c4++) {
            float4 hh[8];
#pragma unroll
            for (int e = 0; e < 8; e++) hh[e] = *(const float4*)(sHw + e * 76 + 4 * c4);
#pragma unroll
            for (int ci = 0; ci < 4; ci++) {
                int c = 4 * c4 + ci;
                float4 wv = sW2f[c * 32 + l];
                ull wlo = pk2(wv.x, wv.y), whi = pk2(wv.z, wv.w);
#pragma unroll
                for (int e = 0; e < 8; e++) {
                    float hv = (ci == 0) ? hh[e].x : (ci == 1) ? hh[e].y : (ci == 2) ? hh[e].z : hh[e].w;
                    ull d = dup2(hv);
                    ma[e] = fma2(d, wlo, ma[e]);
                    mb[e] = fma2(d, whi, mb[e]);
                }
            }
        }
#pragma unroll
        for (int e = 0; e < 8; e++) {
            float2 MA = up2(ma[e]), MB = up2(mb[e]);
            __stcs((float4*)outE + (size_t)(ge0 + e) * 32 + l,
                   make_float4(MA.x, MA.y, MB.x, MB.y));
        }
    }
}

// node output MLP
__global__ void __launch_bounds__(256, 2)
k_nodeout(const float* __restrict__ bn1, const float* __restrict__ Wn2,
          const float* __restrict__ bn2, float* __restrict__ outN) {
    extern __shared__ float sm[];
    ull*    sW1u = (ull*)sm;
    float4* sW2f = (float4*)(sm + 4096);
    float*  sH   = sm + 12288;
    for (int i = threadIdx.x; i < 64 * 32; i += 256) sW1u[i] = g_Wn64[i];
    for (int i = threadIdx.x; i < 64 * 32; i += 256) {
        int j = i >> 5, l = i & 31;
        sW2f[i] = make_float4(Wn2[j * 128 + 4 * l], Wn2[j * 128 + 4 * l + 1],
                              Wn2[j * 128 + 4 * l + 2], Wn2[j * 128 + 4 * l + 3]);
    }
    const int warp = threadIdx.x >> 5, l = threadIdx.x & 31;
    const ull bbu   = pk2(__ldg(bn1 + l), __ldg(bn1 + l + 32));
    const ull baddu = g_bn64[l];
    const ull b2lo = pk2(__ldg(bn2 + 4 * l), __ldg(bn2 + 4 * l + 1));
    const ull b2hi = pk2(__ldg(bn2 + 4 * l + 2), __ldg(bn2 + 4 * l + 3));
    __syncthreads();

    float* sHw = sH + warp * 576;
    const ull* Pnu = (const ull*)g_Pn;
    const int nchunks = (BSZ * NN) / 8;
    for (int w = blockIdx.x * 8 + warp; w < nchunks; w += gridDim.x * 8) {
        const int r0 = w * 8;
        float den8[8];
        ull pn[8];
#pragma unroll
        for (int e = 0; e < 8; e++) {
            den8[e] = __ldg(g_den + r0 + e);
            pn[e] = __ldg(Pnu + (size_t)(r0 + e) * 32 + l);
        }
        ull h[8] = {0ULL, 0ULL, 0ULL, 0ULL, 0ULL, 0ULL, 0ULL, 0ULL};
        const float4* Af = (const float4*)g_agg + (size_t)r0 * 16;
#pragma unroll 4
        for (int k4 = 0; k4 < 16; k4++) {
            ull wk[4];
#pragma unroll
            for (int ki = 0; ki < 4; ki++) wk[ki] = sW1u[(k4 * 4 + ki) * 32 + l];
#pragma unroll
            for (int e = 0; e < 8; e++) {
                float4 v = __ldcs(Af + e * 16 + k4);
                h[e] = fma2(dup2(v.x), wk[0], h[e]);
                h[e] = fma2(dup2(v.y), wk[1], h[e]);
                h[e] = fma2(dup2(v.z), wk[2], h[e]);
                h[e] = fma2(dup2(v.w), wk[3], h[e]);
            }
        }
        __syncwarp();
#pragma unroll
        for (int e = 0; e < 8; e++) {
            float nz = den8[e] != 0.f ? 1.f : 0.f;
            float inv = den8[e] != 0.f ? 1.f / den8[e] : 0.f;
            ull base = add2(pn[e], bbu);
            base = fma2(dup2(nz), baddu, base);
            float2 hh = up2(fma2(dup2(inv), h[e], base));
            sHw[e * 72 + l] = silu_f(hh.x);
            sHw[e * 72 + l + 32] = silu_f(hh.y);
        }
        __syncwarp();
        ull ma[8], mb[8];
#pragma unroll
        for (int e = 0; e < 8; e++) { ma[e] = b2lo; mb[e] = b2hi; }
#pragma unroll 2
        for (int c4 = 0; c4 < 16; c4++) {
            float4 hh[8];
#pragma unroll
            for (int e = 0; e < 8; e++) hh[e] = *(const float4*)(sHw + e * 72 + 4 * c4);
#pragma unroll
            for (int ci = 0; ci < 4; ci++) {
                int c = 4 * c4 + ci;
                float4 wv = sW2f[c * 32 + l];
                ull wlo = pk2(wv.x, wv.y), whi = pk2(wv.z, wv.w);
#pragma unroll
                for (int e = 0; e < 8; e++) {
                    float hv = (ci == 0) ? hh[e].x : (ci == 1) ? hh[e].y : (ci == 2) ? hh[e].z : hh[e].w;
                    ull d = dup2(hv);
                    ma[e] = fma2(d, wlo, ma[e]);
                    mb[e] = fma2(d, whi, mb[e]);
                }
            }
        }
#pragma unroll
        for (int e = 0; e < 8; e++) {
            float2 MA = up2(ma[e]), MB = up2(mb[e]);
            __stcs((float4*)outN + (size_t)(r0 + e) * 32 + l,
                   make_float4(MA.x, MA.y, MB.x, MB.y));
        }
        __syncwarp();
    }
}

extern "C" void kernel_launch(void* const* d_in, const int* in_sizes, int n_in,
                              void* d_out, int out_size) {
    const float* V = (const float*)d_in[0];
    const float* E = (const float*)d_in[1];
    const int* edges = (const int*)d_in[2];
    const float* Wm1 = (const float*)d_in[3];
    const float* bm1 = (const float*)d_in[4];
    const float* Wm2 = (const float*)d_in[5];
    const float* bm2 = (const float*)d_in[6];
    const float* Wa1 = (const float*)d_in[7];
    const float* ba1 = (const float*)d_in[8];
    const float* Wa2 = (const float*)d_in[9];
    const float* ba2 = (const float*)d_in[10];
    const float* Wu1 = (const float*)d_in[11];
    const float* bu1 = (const float*)d_in[12];
    const float* Wu2 = (const float*)d_in[13];
    const float* bu2 = (const float*)d_in[14];
    const float* Wn1 = (const float*)d_in[15];
    const float* bn1 = (const float*)d_in[16];
    const float* Wn2 = (const float*)d_in[17];
    const float* bn2 = (const float*)d_in[18];
    float* outN = (float*)d_out;
    float* outE = outN + (size_t)BSZ * NN * 128;

    float* Pc; cudaGetSymbolAddress((void**)&Pc, g_P);
    float* Pn; cudaGetSymbolAddress((void**)&Pn, g_Pn);

    cudaFuncSetAttribute(k_npre3, cudaFuncAttributeMaxDynamicSharedMemorySize, 196608);
    cudaFuncSetAttribute(k_edge_fused, cudaFuncAttributeMaxDynamicSharedMemorySize, 168064);
    cudaFuncSetAttribute(k_nodeout, cudaFuncAttributeMaxDynamicSharedMemorySize, 67584);

    k_fuseall<<<13, 256>>>(Wm2, bm2, Wa1, ba1, Wn1 + 128 * 64);
    k_npre3<<<148, 512, 196608>>>(V, Wm1, Wu1, Wn1, Pc, Pn);
    k_edge_fused<<<148, 512, 168064>>>(E, edges, Wm1, bm1, Wu1, bu1, Wu2, bu2, Wa2, ba2, Pc, outE);
    k_nodeout<<<592, 256, 67584>>>(bn1, Wn2, bn2, outN);
}